// round 11
// baseline (speedup 1.0000x reference)
#include <cuda_runtime.h>

// ---------------------------------------------------------------------------
// Router_15942918603252 — fused recurrent MoE router, fp32 SIMT baseline.
//
// Shapes: B=16384, IN=512, H=1024, OUT=512, M=8, R=256, max_cycles=4.
//
//   h = x @ W_in + b_in ; orig = h
//   repeat c = 0..max_cycles-1:
//     cp    = c*Wc + bc                                  [H]
//     r     = relu(orig @ (diag(cp) @ Wr1) + br1)        [B,R]
//     probs = softmax(r @ Wr2 + br2)                     [B,M]
//     h     = sum_m probs[:,m] * relu(h @ W_mod[m] + b_mod[m])
//   out = h @ W_out + b_out
//
// All GEMMs: 128x128 CTA tile, K-step 16, double-buffered SMEM, 256 threads,
// 8x8 per-thread micro-tile. Expert GEMM fuses all 8 experts + weighted sum.
// max_cycles is read DEVICE-side (graph-capture safe); per-cycle kernels are
// predicated, h ping-pongs g_h0/g_h1, final GEMM selects source by parity.
// ---------------------------------------------------------------------------

#define DINL __device__ __forceinline__

constexpr int BSZ  = 16384;
constexpr int IND  = 512;
constexpr int HD   = 1024;
constexpr int OUTD = 512;
constexpr int MEXP = 8;
constexpr int RD   = 256;
constexpr int MAX_CYC = 4;   // setup_inputs() fixes max_cycles = 4

// Scratch (device globals — no allocation allowed in kernel_launch).
__device__ float g_h0[(size_t)BSZ * HD];
__device__ float g_h1[(size_t)BSZ * HD];
__device__ float g_orig[(size_t)BSZ * HD];
__device__ float g_r[(size_t)BSZ * RD];
__device__ float g_probs[(size_t)BSZ * MEXP];
__device__ float g_cpW[HD * RD];

// ---------------------------------------------------------------------------
// Core 128x128 tile GEMM inner loop: acc[8][8] += A[row0:+128, :K] * B[:K, col0:+128]
// A is [*, K] row-major, B is [K, N] row-major. K % 16 == 0, N % 128 == 0.
// ---------------------------------------------------------------------------
template<int K, int N>
DINL void mm_tile(const float* __restrict__ A, const float* __restrict__ Bg,
                  int row0, int col0, float acc[8][8],
                  float As[2][16][128], float Bs[2][16][128])
{
    const int tid = threadIdx.x;
    const int ty = tid >> 4, tx = tid & 15;
    const int ar = tid >> 1, ac = (tid & 1) * 8;   // A: 128 rows x 16 k
    const int bk = tid >> 4, bn = (tid & 15) * 8;  // B: 16 k rows x 128 cols

    const float* ap = A + (size_t)(row0 + ar) * K + ac;
    const float* bp = Bg + (size_t)bk * N + col0 + bn;

    float4 a0 = *(const float4*)ap;
    float4 a1 = *(const float4*)(ap + 4);
    float4 b0 = *(const float4*)bp;
    float4 b1 = *(const float4*)(bp + 4);

    constexpr int NK = K / 16;
    int buf = 0;
    As[0][ac + 0][ar] = a0.x; As[0][ac + 1][ar] = a0.y;
    As[0][ac + 2][ar] = a0.z; As[0][ac + 3][ar] = a0.w;
    As[0][ac + 4][ar] = a1.x; As[0][ac + 5][ar] = a1.y;
    As[0][ac + 6][ar] = a1.z; As[0][ac + 7][ar] = a1.w;
    *(float4*)&Bs[0][bk][bn]     = b0;
    *(float4*)&Bs[0][bk][bn + 4] = b1;
    __syncthreads();

    #pragma unroll 1
    for (int kt = 0; kt < NK; ++kt) {
        if (kt + 1 < NK) {
            const float* ap2 = ap + (kt + 1) * 16;
            const float* bp2 = bp + (size_t)(kt + 1) * 16 * N;
            a0 = *(const float4*)ap2;
            a1 = *(const float4*)(ap2 + 4);
            b0 = *(const float4*)bp2;
            b1 = *(const float4*)(bp2 + 4);
        }
        #pragma unroll
        for (int kk = 0; kk < 16; ++kk) {
            float a[8], b[8];
            #pragma unroll
            for (int i = 0; i < 8; ++i) a[i] = As[buf][kk][ty * 8 + i];
            #pragma unroll
            for (int j = 0; j < 8; ++j) b[j] = Bs[buf][kk][tx * 8 + j];
            #pragma unroll
            for (int i = 0; i < 8; ++i)
                #pragma unroll
                for (int j = 0; j < 8; ++j)
                    acc[i][j] = fmaf(a[i], b[j], acc[i][j]);
        }
        if (kt + 1 < NK) {
            buf ^= 1;
            As[buf][ac + 0][ar] = a0.x; As[buf][ac + 1][ar] = a0.y;
            As[buf][ac + 2][ar] = a0.z; As[buf][ac + 3][ar] = a0.w;
            As[buf][ac + 4][ar] = a1.x; As[buf][ac + 5][ar] = a1.y;
            As[buf][ac + 6][ar] = a1.z; As[buf][ac + 7][ar] = a1.w;
            *(float4*)&Bs[buf][bk][bn]     = b0;
            *(float4*)&Bs[buf][bk][bn + 4] = b1;
        }
        __syncthreads();
    }
}

DINL void zero88(float a[8][8]) {
    #pragma unroll
    for (int i = 0; i < 8; ++i)
        #pragma unroll
        for (int j = 0; j < 8; ++j) a[i][j] = 0.f;
}

// ---------------------------------------------------------------------------
// h = x @ W_in + b_in  -> g_h0 and g_orig
// ---------------------------------------------------------------------------
__global__ __launch_bounds__(256, 1)
void k_gemm_in(const float* __restrict__ x, const float* __restrict__ W,
               const float* __restrict__ bias)
{
    __shared__ __align__(16) float As[2][16][128];
    __shared__ __align__(16) float Bs[2][16][128];
    const int row0 = blockIdx.y * 128, col0 = blockIdx.x * 128;
    float acc[8][8]; zero88(acc);
    mm_tile<IND, HD>(x, W, row0, col0, acc, As, Bs);

    const int tid = threadIdx.x, ty = tid >> 4, tx = tid & 15;
    float bv[8];
    #pragma unroll
    for (int j = 0; j < 8; ++j) bv[j] = bias[col0 + tx * 8 + j];
    #pragma unroll
    for (int i = 0; i < 8; ++i) {
        const size_t off = (size_t)(row0 + ty * 8 + i) * HD + col0 + tx * 8;
        float4 o0 = make_float4(acc[i][0] + bv[0], acc[i][1] + bv[1],
                                acc[i][2] + bv[2], acc[i][3] + bv[3]);
        float4 o1 = make_float4(acc[i][4] + bv[4], acc[i][5] + bv[5],
                                acc[i][6] + bv[6], acc[i][7] + bv[7]);
        *(float4*)(g_h0 + off)     = o0;
        *(float4*)(g_h0 + off + 4) = o1;
        *(float4*)(g_orig + off)     = o0;
        *(float4*)(g_orig + off + 4) = o1;
    }
}

// ---------------------------------------------------------------------------
// cpW[h][j] = (c*Wc[h] + bc[h]) * Wr1[h][j]   (folds cycle projection into Wr1)
// ---------------------------------------------------------------------------
__global__ void k_modw(const float* __restrict__ Wc, const float* __restrict__ bc,
                       const float* __restrict__ Wr1, float cval,
                       const int* __restrict__ mcp, int cycle)
{
    if (cycle >= __ldg(mcp)) return;
    const int idx = blockIdx.x * 256 + threadIdx.x;   // HD*RD threads total
    const int h = idx >> 8;                           // RD = 256
    g_cpW[idx] = (cval * Wc[h] + bc[h]) * Wr1[idx];
}

// ---------------------------------------------------------------------------
// r = relu(orig @ cpW + br1)      [B,1024] x [1024,256]
// ---------------------------------------------------------------------------
__global__ __launch_bounds__(256, 1)
void k_gemm_r(const float* __restrict__ br1, const int* __restrict__ mcp, int cycle)
{
    if (cycle >= __ldg(mcp)) return;
    __shared__ __align__(16) float As[2][16][128];
    __shared__ __align__(16) float Bs[2][16][128];
    const int row0 = blockIdx.y * 128, col0 = blockIdx.x * 128;
    float acc[8][8]; zero88(acc);
    mm_tile<HD, RD>(g_orig, g_cpW, row0, col0, acc, As, Bs);

    const int tid = threadIdx.x, ty = tid >> 4, tx = tid & 15;
    float bv[8];
    #pragma unroll
    for (int j = 0; j < 8; ++j) bv[j] = br1[col0 + tx * 8 + j];
    #pragma unroll
    for (int i = 0; i < 8; ++i) {
        const size_t off = (size_t)(row0 + ty * 8 + i) * RD + col0 + tx * 8;
        float4 o0 = make_float4(fmaxf(acc[i][0] + bv[0], 0.f), fmaxf(acc[i][1] + bv[1], 0.f),
                                fmaxf(acc[i][2] + bv[2], 0.f), fmaxf(acc[i][3] + bv[3], 0.f));
        float4 o1 = make_float4(fmaxf(acc[i][4] + bv[4], 0.f), fmaxf(acc[i][5] + bv[5], 0.f),
                                fmaxf(acc[i][6] + bv[6], 0.f), fmaxf(acc[i][7] + bv[7], 0.f));
        *(float4*)(g_r + off)     = o0;
        *(float4*)(g_r + off + 4) = o1;
    }
}

// ---------------------------------------------------------------------------
// probs = softmax(r @ Wr2 + br2)  — one warp per batch row (M=8 logits)
// ---------------------------------------------------------------------------
__global__ __launch_bounds__(256, 1)
void k_router(const float* __restrict__ Wr2, const float* __restrict__ br2,
              const int* __restrict__ mcp, int cycle)
{
    if (cycle >= __ldg(mcp)) return;
    __shared__ __align__(16) float w2t[8][256];
    __shared__ float sb2[8];
    const int tid = threadIdx.x;
    {
        // Wr2 is [256, 8] row-major: thread tid owns row k = tid (8 floats).
        float4 v0 = ((const float4*)Wr2)[tid * 2];
        float4 v1 = ((const float4*)Wr2)[tid * 2 + 1];
        w2t[0][tid] = v0.x; w2t[1][tid] = v0.y; w2t[2][tid] = v0.z; w2t[3][tid] = v0.w;
        w2t[4][tid] = v1.x; w2t[5][tid] = v1.y; w2t[6][tid] = v1.z; w2t[7][tid] = v1.w;
    }
    if (tid < 8) sb2[tid] = br2[tid];
    __syncthreads();

    const int warp = tid >> 5, lane = tid & 31;
    const size_t b = (size_t)blockIdx.x * 8 + warp;

    float s[8];
    #pragma unroll
    for (int m = 0; m < 8; ++m) s[m] = 0.f;
    #pragma unroll
    for (int jj = 0; jj < 8; ++jj) {
        const float rv = g_r[b * RD + jj * 32 + lane];
        #pragma unroll
        for (int m = 0; m < 8; ++m) s[m] += rv * w2t[m][jj * 32 + lane];
    }
    #pragma unroll
    for (int m = 0; m < 8; ++m)
        #pragma unroll
        for (int o = 16; o; o >>= 1) s[m] += __shfl_xor_sync(0xffffffffu, s[m], o);
    #pragma unroll
    for (int m = 0; m < 8; ++m) s[m] += sb2[m];

    float mx = s[0];
    #pragma unroll
    for (int m = 1; m < 8; ++m) mx = fmaxf(mx, s[m]);
    float den = 0.f;
    #pragma unroll
    for (int m = 0; m < 8; ++m) { s[m] = expf(s[m] - mx); den += s[m]; }
    const float inv = 1.f / den;
    if (lane < 8) g_probs[b * 8 + lane] = s[lane] * inv;
}

// ---------------------------------------------------------------------------
// h_new[b,d] = sum_m probs[b,m] * relu(sum_h h[b,h]*W_mod[m,h,d] + b_mod[m,d])
// All 8 experts fused: m-loop outer, weighted-relu accumulated in registers.
// ---------------------------------------------------------------------------
__global__ __launch_bounds__(256, 1)
void k_expert(const float* __restrict__ Wm, const float* __restrict__ bmod,
              const int* __restrict__ mcp, int cycle)
{
    if (cycle >= __ldg(mcp)) return;
    __shared__ __align__(16) float As[2][16][128];
    __shared__ __align__(16) float Bs[2][16][128];
    __shared__ __align__(16) float sprob[128][8];

    const float* __restrict__ Hc = (cycle & 1) ? g_h1 : g_h0;
    float* __restrict__ Hn       = (cycle & 1) ? g_h0 : g_h1;

    const int tid = threadIdx.x;
    const int row0 = blockIdx.y * 128, col0 = blockIdx.x * 128;

    // stage probs tile [128 rows x 8 experts]
    ((float4*)&sprob[0][0])[tid] =
        *(const float4*)(g_probs + (size_t)row0 * MEXP + tid * 4);

    const int ty = tid >> 4, tx = tid & 15;
    float fin[8][8]; zero88(fin);

    #pragma unroll 1
    for (int m = 0; m < MEXP; ++m) {
        float acc[8][8]; zero88(acc);
        mm_tile<HD, HD>(Hc, Wm + (size_t)m * HD * HD, row0, col0, acc, As, Bs);

        float bv[8];
        #pragma unroll
        for (int j = 0; j < 8; ++j) bv[j] = bmod[m * HD + col0 + tx * 8 + j];
        #pragma unroll
        for (int i = 0; i < 8; ++i) {
            const float p = sprob[ty * 8 + i][m];
            #pragma unroll
            for (int j = 0; j < 8; ++j)
                fin[i][j] += p * fmaxf(acc[i][j] + bv[j], 0.f);
        }
    }

    #pragma unroll
    for (int i = 0; i < 8; ++i) {
        const size_t off = (size_t)(row0 + ty * 8 + i) * HD + col0 + tx * 8;
        *(float4*)(Hn + off)     = make_float4(fin[i][0], fin[i][1], fin[i][2], fin[i][3]);
        *(float4*)(Hn + off + 4) = make_float4(fin[i][4], fin[i][5], fin[i][6], fin[i][7]);
    }
}

// ---------------------------------------------------------------------------
// out = h_final @ W_out + b_out   (h_final = g_h[max_cycles & 1], device-side)
// ---------------------------------------------------------------------------
__global__ __launch_bounds__(256, 1)
void k_gemm_out(const float* __restrict__ W, const float* __restrict__ bias,
                float* __restrict__ out, const int* __restrict__ mcp)
{
    __shared__ __align__(16) float As[2][16][128];
    __shared__ __align__(16) float Bs[2][16][128];
    const float* __restrict__ A = (__ldg(mcp) & 1) ? g_h1 : g_h0;
    const int row0 = blockIdx.y * 128, col0 = blockIdx.x * 128;
    float acc[8][8]; zero88(acc);
    mm_tile<HD, OUTD>(A, W, row0, col0, acc, As, Bs);

    const int tid = threadIdx.x, ty = tid >> 4, tx = tid & 15;
    float bv[8];
    #pragma unroll
    for (int j = 0; j < 8; ++j) bv[j] = bias[col0 + tx * 8 + j];
    #pragma unroll
    for (int i = 0; i < 8; ++i) {
        const size_t off = (size_t)(row0 + ty * 8 + i) * OUTD + col0 + tx * 8;
        *(float4*)(out + off)     = make_float4(acc[i][0] + bv[0], acc[i][1] + bv[1],
                                                acc[i][2] + bv[2], acc[i][3] + bv[3]);
        *(float4*)(out + off + 4) = make_float4(acc[i][4] + bv[4], acc[i][5] + bv[5],
                                                acc[i][6] + bv[6], acc[i][7] + bv[7]);
    }
}

// ---------------------------------------------------------------------------
extern "C" void kernel_launch(void* const* d_in, const int* in_sizes, int n_in,
                              void* d_out, int out_size)
{
    const float* x     = (const float*)d_in[0];
    const float* W_in  = (const float*)d_in[1];
    const float* b_in  = (const float*)d_in[2];
    const float* W_mod = (const float*)d_in[3];
    const float* b_mod = (const float*)d_in[4];
    const float* Wr1   = (const float*)d_in[5];
    const float* br1   = (const float*)d_in[6];
    const float* Wr2   = (const float*)d_in[7];
    const float* br2   = (const float*)d_in[8];
    const float* Wc    = (const float*)d_in[9];
    const float* bc    = (const float*)d_in[10];
    const float* W_out = (const float*)d_in[11];
    const float* b_out = (const float*)d_in[12];
    const int*   mcp   = (const int*)d_in[13];
    float* out = (float*)d_out;

    const dim3 blk(256);

    // h = x @ W_in + b_in  (also stores orig)
    k_gemm_in<<<dim3(HD / 128, BSZ / 128), blk>>>(x, W_in, b_in);

    // Recurrent cycles (device-predicated on *mcp; structure fixed for capture)
    for (int c = 0; c < MAX_CYC; ++c) {
        k_modw  <<<(HD * RD) / 256, blk>>>(Wc, bc, Wr1, (float)c, mcp, c);
        k_gemm_r<<<dim3(RD / 128, BSZ / 128), blk>>>(br1, mcp, c);
        k_router<<<BSZ / 8, blk>>>(Wr2, br2, mcp, c);
        k_expert<<<dim3(HD / 128, BSZ / 128), blk>>>(W_mod, b_mod, mcp, c);
    }

    // out = h @ W_out + b_out (source buffer selected by parity device-side)
    k_gemm_out<<<dim3(OUTD / 128, BSZ / 128), blk>>>(W_out, b_out, out, mcp);
}

// round 12
// speedup vs baseline: 1.0015x; 1.0015x over previous
#include <cuda_runtime.h>

// ---------------------------------------------------------------------------
// Router_15942918603252 — fused recurrent MoE router, fp32 SIMT baseline.
//
// Shapes: B=16384, IN=512, H=1024, OUT=512, M=8, R=256, max_cycles=4.
//
//   h = x @ W_in + b_in ; orig = h
//   repeat c = 0..max_cycles-1:
//     cp    = c*Wc + bc                                  [H]
//     r     = relu(orig @ (diag(cp) @ Wr1) + br1)        [B,R]
//     probs = softmax(r @ Wr2 + br2)                     [B,M]
//     h     = sum_m probs[:,m] * relu(h @ W_mod[m] + b_mod[m])
//   out = h @ W_out + b_out
//
// All GEMMs: 128x128 CTA tile, K-step 16, double-buffered SMEM, 256 threads,
// 8x8 per-thread micro-tile. Expert GEMM fuses all 8 experts + weighted sum.
// max_cycles is read DEVICE-side (graph-capture safe); per-cycle kernels are
// predicated, h ping-pongs g_h0/g_h1, final GEMM selects source by parity.
// ---------------------------------------------------------------------------

#define DINL __device__ __forceinline__

constexpr int BSZ  = 16384;
constexpr int IND  = 512;
constexpr int HD   = 1024;
constexpr int OUTD = 512;
constexpr int MEXP = 8;
constexpr int RD   = 256;
constexpr int MAX_CYC = 4;   // setup_inputs() fixes max_cycles = 4

// Scratch (device globals — no allocation allowed in kernel_launch).
__device__ float g_h0[(size_t)BSZ * HD];
__device__ float g_h1[(size_t)BSZ * HD];
__device__ float g_orig[(size_t)BSZ * HD];
__device__ float g_r[(size_t)BSZ * RD];
__device__ float g_probs[(size_t)BSZ * MEXP];
__device__ float g_cpW[HD * RD];

// ---------------------------------------------------------------------------
// Core 128x128 tile GEMM inner loop: acc[8][8] += A[row0:+128, :K] * B[:K, col0:+128]
// A is [*, K] row-major, B is [K, N] row-major. K % 16 == 0, N % 128 == 0.
// ---------------------------------------------------------------------------
template<int K, int N>
DINL void mm_tile(const float* __restrict__ A, const float* __restrict__ Bg,
                  int row0, int col0, float acc[8][8],
                  float As[2][16][128], float Bs[2][16][128])
{
    const int tid = threadIdx.x;
    const int ty = tid >> 4, tx = tid & 15;
    const int ar = tid >> 1, ac = (tid & 1) * 8;   // A: 128 rows x 16 k
    const int bk = tid >> 4, bn = (tid & 15) * 8;  // B: 16 k rows x 128 cols

    const float* ap = A + (size_t)(row0 + ar) * K + ac;
    const float* bp = Bg + (size_t)bk * N + col0 + bn;

    float4 a0 = *(const float4*)ap;
    float4 a1 = *(const float4*)(ap + 4);
    float4 b0 = *(const float4*)bp;
    float4 b1 = *(const float4*)(bp + 4);

    constexpr int NK = K / 16;
    int buf = 0;
    As[0][ac + 0][ar] = a0.x; As[0][ac + 1][ar] = a0.y;
    As[0][ac + 2][ar] = a0.z; As[0][ac + 3][ar] = a0.w;
    As[0][ac + 4][ar] = a1.x; As[0][ac + 5][ar] = a1.y;
    As[0][ac + 6][ar] = a1.z; As[0][ac + 7][ar] = a1.w;
    *(float4*)&Bs[0][bk][bn]     = b0;
    *(float4*)&Bs[0][bk][bn + 4] = b1;
    __syncthreads();

    #pragma unroll 1
    for (int kt = 0; kt < NK; ++kt) {
        if (kt + 1 < NK) {
            const float* ap2 = ap + (kt + 1) * 16;
            const float* bp2 = bp + (size_t)(kt + 1) * 16 * N;
            a0 = *(const float4*)ap2;
            a1 = *(const float4*)(ap2 + 4);
            b0 = *(const float4*)bp2;
            b1 = *(const float4*)(bp2 + 4);
        }
        #pragma unroll
        for (int kk = 0; kk < 16; ++kk) {
            float a[8], b[8];
            #pragma unroll
            for (int i = 0; i < 8; ++i) a[i] = As[buf][kk][ty * 8 + i];
            #pragma unroll
            for (int j = 0; j < 8; ++j) b[j] = Bs[buf][kk][tx * 8 + j];
            #pragma unroll
            for (int i = 0; i < 8; ++i)
                #pragma unroll
                for (int j = 0; j < 8; ++j)
                    acc[i][j] = fmaf(a[i], b[j], acc[i][j]);
        }
        if (kt + 1 < NK) {
            buf ^= 1;
            As[buf][ac + 0][ar] = a0.x; As[buf][ac + 1][ar] = a0.y;
            As[buf][ac + 2][ar] = a0.z; As[buf][ac + 3][ar] = a0.w;
            As[buf][ac + 4][ar] = a1.x; As[buf][ac + 5][ar] = a1.y;
            As[buf][ac + 6][ar] = a1.z; As[buf][ac + 7][ar] = a1.w;
            *(float4*)&Bs[buf][bk][bn]     = b0;
            *(float4*)&Bs[buf][bk][bn + 4] = b1;
        }
        __syncthreads();
    }
}

DINL void zero88(float a[8][8]) {
    #pragma unroll
    for (int i = 0; i < 8; ++i)
        #pragma unroll
        for (int j = 0; j < 8; ++j) a[i][j] = 0.f;
}

// ---------------------------------------------------------------------------
// h = x @ W_in + b_in  -> g_h0 and g_orig
// ---------------------------------------------------------------------------
__global__ __launch_bounds__(256, 1)
void k_gemm_in(const float* __restrict__ x, const float* __restrict__ W,
               const float* __restrict__ bias)
{
    __shared__ __align__(16) float As[2][16][128];
    __shared__ __align__(16) float Bs[2][16][128];
    const int row0 = blockIdx.y * 128, col0 = blockIdx.x * 128;
    float acc[8][8]; zero88(acc);
    mm_tile<IND, HD>(x, W, row0, col0, acc, As, Bs);

    const int tid = threadIdx.x, ty = tid >> 4, tx = tid & 15;
    float bv[8];
    #pragma unroll
    for (int j = 0; j < 8; ++j) bv[j] = bias[col0 + tx * 8 + j];
    #pragma unroll
    for (int i = 0; i < 8; ++i) {
        const size_t off = (size_t)(row0 + ty * 8 + i) * HD + col0 + tx * 8;
        float4 o0 = make_float4(acc[i][0] + bv[0], acc[i][1] + bv[1],
                                acc[i][2] + bv[2], acc[i][3] + bv[3]);
        float4 o1 = make_float4(acc[i][4] + bv[4], acc[i][5] + bv[5],
                                acc[i][6] + bv[6], acc[i][7] + bv[7]);
        *(float4*)(g_h0 + off)     = o0;
        *(float4*)(g_h0 + off + 4) = o1;
        *(float4*)(g_orig + off)     = o0;
        *(float4*)(g_orig + off + 4) = o1;
    }
}

// ---------------------------------------------------------------------------
// cpW[h][j] = (c*Wc[h] + bc[h]) * Wr1[h][j]   (folds cycle projection into Wr1)
// ---------------------------------------------------------------------------
__global__ void k_modw(const float* __restrict__ Wc, const float* __restrict__ bc,
                       const float* __restrict__ Wr1, float cval,
                       const int* __restrict__ mcp, int cycle)
{
    if (cycle >= __ldg(mcp)) return;
    const int idx = blockIdx.x * 256 + threadIdx.x;   // HD*RD threads total
    const int h = idx >> 8;                           // RD = 256
    g_cpW[idx] = (cval * Wc[h] + bc[h]) * Wr1[idx];
}

// ---------------------------------------------------------------------------
// r = relu(orig @ cpW + br1)      [B,1024] x [1024,256]
// ---------------------------------------------------------------------------
__global__ __launch_bounds__(256, 1)
void k_gemm_r(const float* __restrict__ br1, const int* __restrict__ mcp, int cycle)
{
    if (cycle >= __ldg(mcp)) return;
    __shared__ __align__(16) float As[2][16][128];
    __shared__ __align__(16) float Bs[2][16][128];
    const int row0 = blockIdx.y * 128, col0 = blockIdx.x * 128;
    float acc[8][8]; zero88(acc);
    mm_tile<HD, RD>(g_orig, g_cpW, row0, col0, acc, As, Bs);

    const int tid = threadIdx.x, ty = tid >> 4, tx = tid & 15;
    float bv[8];
    #pragma unroll
    for (int j = 0; j < 8; ++j) bv[j] = br1[col0 + tx * 8 + j];
    #pragma unroll
    for (int i = 0; i < 8; ++i) {
        const size_t off = (size_t)(row0 + ty * 8 + i) * RD + col0 + tx * 8;
        float4 o0 = make_float4(fmaxf(acc[i][0] + bv[0], 0.f), fmaxf(acc[i][1] + bv[1], 0.f),
                                fmaxf(acc[i][2] + bv[2], 0.f), fmaxf(acc[i][3] + bv[3], 0.f));
        float4 o1 = make_float4(fmaxf(acc[i][4] + bv[4], 0.f), fmaxf(acc[i][5] + bv[5], 0.f),
                                fmaxf(acc[i][6] + bv[6], 0.f), fmaxf(acc[i][7] + bv[7], 0.f));
        *(float4*)(g_r + off)     = o0;
        *(float4*)(g_r + off + 4) = o1;
    }
}

// ---------------------------------------------------------------------------
// probs = softmax(r @ Wr2 + br2)  — one warp per batch row (M=8 logits)
// ---------------------------------------------------------------------------
__global__ __launch_bounds__(256, 1)
void k_router(const float* __restrict__ Wr2, const float* __restrict__ br2,
              const int* __restrict__ mcp, int cycle)
{
    if (cycle >= __ldg(mcp)) return;
    __shared__ __align__(16) float w2t[8][256];
    __shared__ float sb2[8];
    const int tid = threadIdx.x;
    {
        // Wr2 is [256, 8] row-major: thread tid owns row k = tid (8 floats).
        float4 v0 = ((const float4*)Wr2)[tid * 2];
        float4 v1 = ((const float4*)Wr2)[tid * 2 + 1];
        w2t[0][tid] = v0.x; w2t[1][tid] = v0.y; w2t[2][tid] = v0.z; w2t[3][tid] = v0.w;
        w2t[4][tid] = v1.x; w2t[5][tid] = v1.y; w2t[6][tid] = v1.z; w2t[7][tid] = v1.w;
    }
    if (tid < 8) sb2[tid] = br2[tid];
    __syncthreads();

    const int warp = tid >> 5, lane = tid & 31;
    const size_t b = (size_t)blockIdx.x * 8 + warp;

    float s[8];
    #pragma unroll
    for (int m = 0; m < 8; ++m) s[m] = 0.f;
    #pragma unroll
    for (int jj = 0; jj < 8; ++jj) {
        const float rv = g_r[b * RD + jj * 32 + lane];
        #pragma unroll
        for (int m = 0; m < 8; ++m) s[m] += rv * w2t[m][jj * 32 + lane];
    }
    #pragma unroll
    for (int m = 0; m < 8; ++m)
        #pragma unroll
        for (int o = 16; o; o >>= 1) s[m] += __shfl_xor_sync(0xffffffffu, s[m], o);
    #pragma unroll
    for (int m = 0; m < 8; ++m) s[m] += sb2[m];

    float mx = s[0];
    #pragma unroll
    for (int m = 1; m < 8; ++m) mx = fmaxf(mx, s[m]);
    float den = 0.f;
    #pragma unroll
    for (int m = 0; m < 8; ++m) { s[m] = expf(s[m] - mx); den += s[m]; }
    const float inv = 1.f / den;
    if (lane < 8) g_probs[b * 8 + lane] = s[lane] * inv;
}

// ---------------------------------------------------------------------------
// h_new[b,d] = sum_m probs[b,m] * relu(sum_h h[b,h]*W_mod[m,h,d] + b_mod[m,d])
// All 8 experts fused: m-loop outer, weighted-relu accumulated in registers.
// ---------------------------------------------------------------------------
__global__ __launch_bounds__(256, 1)
void k_expert(const float* __restrict__ Wm, const float* __restrict__ bmod,
              const int* __restrict__ mcp, int cycle)
{
    if (cycle >= __ldg(mcp)) return;
    __shared__ __align__(16) float As[2][16][128];
    __shared__ __align__(16) float Bs[2][16][128];
    __shared__ __align__(16) float sprob[128][8];

    const float* __restrict__ Hc = (cycle & 1) ? g_h1 : g_h0;
    float* __restrict__ Hn       = (cycle & 1) ? g_h0 : g_h1;

    const int tid = threadIdx.x;
    const int row0 = blockIdx.y * 128, col0 = blockIdx.x * 128;

    // stage probs tile [128 rows x 8 experts]
    ((float4*)&sprob[0][0])[tid] =
        *(const float4*)(g_probs + (size_t)row0 * MEXP + tid * 4);

    const int ty = tid >> 4, tx = tid & 15;
    float fin[8][8]; zero88(fin);

    #pragma unroll 1
    for (int m = 0; m < MEXP; ++m) {
        float acc[8][8]; zero88(acc);
        mm_tile<HD, HD>(Hc, Wm + (size_t)m * HD * HD, row0, col0, acc, As, Bs);

        float bv[8];
        #pragma unroll
        for (int j = 0; j < 8; ++j) bv[j] = bmod[m * HD + col0 + tx * 8 + j];
        #pragma unroll
        for (int i = 0; i < 8; ++i) {
            const float p = sprob[ty * 8 + i][m];
            #pragma unroll
            for (int j = 0; j < 8; ++j)
                fin[i][j] += p * fmaxf(acc[i][j] + bv[j], 0.f);
        }
    }

    #pragma unroll
    for (int i = 0; i < 8; ++i) {
        const size_t off = (size_t)(row0 + ty * 8 + i) * HD + col0 + tx * 8;
        *(float4*)(Hn + off)     = make_float4(fin[i][0], fin[i][1], fin[i][2], fin[i][3]);
        *(float4*)(Hn + off + 4) = make_float4(fin[i][4], fin[i][5], fin[i][6], fin[i][7]);
    }
}

// ---------------------------------------------------------------------------
// out = h_final @ W_out + b_out   (h_final = g_h[max_cycles & 1], device-side)
// ---------------------------------------------------------------------------
__global__ __launch_bounds__(256, 1)
void k_gemm_out(const float* __restrict__ W, const float* __restrict__ bias,
                float* __restrict__ out, const int* __restrict__ mcp)
{
    __shared__ __align__(16) float As[2][16][128];
    __shared__ __align__(16) float Bs[2][16][128];
    const float* __restrict__ A = (__ldg(mcp) & 1) ? g_h1 : g_h0;
    const int row0 = blockIdx.y * 128, col0 = blockIdx.x * 128;
    float acc[8][8]; zero88(acc);
    mm_tile<HD, OUTD>(A, W, row0, col0, acc, As, Bs);

    const int tid = threadIdx.x, ty = tid >> 4, tx = tid & 15;
    float bv[8];
    #pragma unroll
    for (int j = 0; j < 8; ++j) bv[j] = bias[col0 + tx * 8 + j];
    #pragma unroll
    for (int i = 0; i < 8; ++i) {
        const size_t off = (size_t)(row0 + ty * 8 + i) * OUTD + col0 + tx * 8;
        *(float4*)(out + off)     = make_float4(acc[i][0] + bv[0], acc[i][1] + bv[1],
                                                acc[i][2] + bv[2], acc[i][3] + bv[3]);
        *(float4*)(out + off + 4) = make_float4(acc[i][4] + bv[4], acc[i][5] + bv[5],
                                                acc[i][6] + bv[6], acc[i][7] + bv[7]);
    }
}

// ---------------------------------------------------------------------------
extern "C" void kernel_launch(void* const* d_in, const int* in_sizes, int n_in,
                              void* d_out, int out_size)
{
    const float* x     = (const float*)d_in[0];
    const float* W_in  = (const float*)d_in[1];
    const float* b_in  = (const float*)d_in[2];
    const float* W_mod = (const float*)d_in[3];
    const float* b_mod = (const float*)d_in[4];
    const float* Wr1   = (const float*)d_in[5];
    const float* br1   = (const float*)d_in[6];
    const float* Wr2   = (const float*)d_in[7];
    const float* br2   = (const float*)d_in[8];
    const float* Wc    = (const float*)d_in[9];
    const float* bc    = (const float*)d_in[10];
    const float* W_out = (const float*)d_in[11];
    const float* b_out = (const float*)d_in[12];
    const int*   mcp   = (const int*)d_in[13];
    float* out = (float*)d_out;

    const dim3 blk(256);

    // h = x @ W_in + b_in  (also stores orig)
    k_gemm_in<<<dim3(HD / 128, BSZ / 128), blk>>>(x, W_in, b_in);

    // Recurrent cycles (device-predicated on *mcp; structure fixed for capture)
    for (int c = 0; c < MAX_CYC; ++c) {
        k_modw  <<<(HD * RD) / 256, blk>>>(Wc, bc, Wr1, (float)c, mcp, c);
        k_gemm_r<<<dim3(RD / 128, BSZ / 128), blk>>>(br1, mcp, c);
        k_router<<<BSZ / 8, blk>>>(Wr2, br2, mcp, c);
        k_expert<<<dim3(HD / 128, BSZ / 128), blk>>>(W_mod, b_mod, mcp, c);
    }

    // out = h @ W_out + b_out (source buffer selected by parity device-side)
    k_gemm_out<<<dim3(OUTD / 128, BSZ / 128), blk>>>(W_out, b_out, out, mcp);
}